// round 11
// baseline (speedup 1.0000x reference)
#include <cuda_runtime.h>
#include <math.h>

#define NLEV   16
#define TSZ    524288
#define HIDDEN 64
#define FEAT   13
#define DIN    35
#define MAXN   1048576
#define NBUCK  262144          // 64^3 Morton buckets

typedef unsigned long long u64;

__device__ __forceinline__ u64 pack2(float lo, float hi) {
    u64 r; asm("mov.b64 %0, {%1, %2};" : "=l"(r) : "f"(lo), "f"(hi)); return r;
}
__device__ __forceinline__ u64 bcast2(float v) { return pack2(v, v); }
__device__ __forceinline__ u64 fma2(u64 a, u64 b, u64 c) {
    u64 d; asm("fma.rn.f32x2 %0, %1, %2, %3;" : "=l"(d) : "l"(a), "l"(b), "l"(c)); return d;
}
__device__ __forceinline__ void unpack2(u64 v, float& lo, float& hi) {
    asm("mov.b64 {%0, %1}, %2;" : "=f"(lo), "=f"(hi) : "l"(v));
}

// ---------------------------------------------------------------------------
// Weight staging + value-packed ulonglong2 forms
// ---------------------------------------------------------------------------
__device__ float g_W0T[DIN][HIDDEN];
__device__ float g_W1T[HIDDEN][HIDDEN];
__device__ float g_W2T[HIDDEN][16];
__device__ float g_b0[HIDDEN];
__device__ float g_b1[HIDDEN];
__device__ float g_b2[16];

__device__ ulonglong2 g_W0p[DIN][16];
__device__ ulonglong2 g_W1p[HIDDEN][16];
__device__ ulonglong2 g_W2p[HIDDEN][4];
__device__ ulonglong2 g_b0p[16];
__device__ ulonglong2 g_b1p[16];
__device__ ulonglong2 g_b2p[4];

// ---------------------------------------------------------------------------
// Morton-sort scratch
// ---------------------------------------------------------------------------
__device__ int   g_hist[NBUCK];
__device__ int   g_off[NBUCK];
__device__ int   g_cell[MAXN];
__device__ int   g_perm[MAXN];      // sorted slot -> original point id
__device__ float g_pts[MAXN * 3];   // points in sorted order

__global__ void prep_kernel(const float* __restrict__ V0, const float* __restrict__ g0, const float* __restrict__ b0,
                            const float* __restrict__ V1, const float* __restrict__ g1, const float* __restrict__ b1,
                            const float* __restrict__ V2, const float* __restrict__ g2, const float* __restrict__ b2)
{
    int o = threadIdx.x;
    if (o < HIDDEN) {
        float s = 0.f;
        for (int i = 0; i < DIN; i++) { float v = V0[o * DIN + i]; s += v * v; }
        float sc = g0[o] / sqrtf(s);
        for (int i = 0; i < DIN; i++) g_W0T[i][o] = V0[o * DIN + i] * sc;
        g_b0[o] = b0[o];

        s = 0.f;
        for (int i = 0; i < HIDDEN; i++) { float v = V1[o * HIDDEN + i]; s += v * v; }
        sc = g1[o] / sqrtf(s);
        for (int i = 0; i < HIDDEN; i++) g_W1T[i][o] = V1[o * HIDDEN + i] * sc;
        g_b1[o] = b1[o];
    }
    if (o < 16) {
        if (o < FEAT) {
            float s = 0.f;
            for (int i = 0; i < HIDDEN; i++) { float v = V2[o * HIDDEN + i]; s += v * v; }
            float sc = g2[o] / sqrtf(s);
            for (int i = 0; i < HIDDEN; i++) g_W2T[i][o] = V2[o * HIDDEN + i] * sc;
            g_b2[o] = b2[o];
        } else {
            for (int i = 0; i < HIDDEN; i++) g_W2T[i][o] = 0.f;
            g_b2[o] = 0.f;
        }
    }
}

__device__ __forceinline__ ulonglong2 pack4(const float* s) {
    ulonglong2 v;
    v.x = ((u64)__float_as_uint(s[1]) << 32) | (u64)__float_as_uint(s[0]);
    v.y = ((u64)__float_as_uint(s[3]) << 32) | (u64)__float_as_uint(s[2]);
    return v;
}

__global__ void pack_kernel()
{
    const int NW0 = DIN * 16, NW1 = HIDDEN * 16, NW2 = HIDDEN * 4;
    const int total = NW0 + NW1 + NW2 + 16 + 16 + 4;
    for (int e = threadIdx.x; e < total; e += blockDim.x) {
        int r = e;
        if (r < NW0) { (&g_W0p[0][0])[r] = pack4(&(&g_W0T[0][0])[4 * r]); continue; }
        r -= NW0;
        if (r < NW1) { (&g_W1p[0][0])[r] = pack4(&(&g_W1T[0][0])[4 * r]); continue; }
        r -= NW1;
        if (r < NW2) { (&g_W2p[0][0])[r] = pack4(&(&g_W2T[0][0])[4 * r]); continue; }
        r -= NW2;
        if (r < 16) { g_b0p[r] = pack4(&g_b0[4 * r]); continue; }
        r -= 16;
        if (r < 16) { g_b1p[r] = pack4(&g_b1[4 * r]); continue; }
        r -= 16;
        g_b2p[r] = pack4(&g_b2[4 * r]);
    }
}

// ---------------------------------------------------------------------------
// Morton counting sort (64^3, 18-bit keys)
// ---------------------------------------------------------------------------
__global__ void zero_hist_kernel()
{
    int i = blockIdx.x * blockDim.x + threadIdx.x;
    if (i < NBUCK) g_hist[i] = 0;
}

__device__ __forceinline__ unsigned expand6(unsigned v)
{
    unsigned r = 0;
    #pragma unroll
    for (int b = 0; b < 6; b++) r |= ((v >> b) & 1u) << (3 * b);
    return r;
}

__global__ void assign_kernel(const float* __restrict__ points, int n)
{
    int i = blockIdx.x * blockDim.x + threadIdx.x;
    if (i >= n) return;
    const float ux = fminf(fmaxf((points[3 * i + 0] + 1.f) * 0.5f, 0.f), 1.f);
    const float uy = fminf(fmaxf((points[3 * i + 1] + 1.f) * 0.5f, 0.f), 1.f);
    const float uz = fminf(fmaxf((points[3 * i + 2] + 1.f) * 0.5f, 0.f), 1.f);
    const unsigned cx = min(63, (int)(ux * 64.f));
    const unsigned cy = min(63, (int)(uy * 64.f));
    const unsigned cz = min(63, (int)(uz * 64.f));
    const int key = (int)(expand6(cx) | (expand6(cy) << 1) | (expand6(cz) << 2));
    g_cell[i] = key;
    atomicAdd(&g_hist[key], 1);
}

__global__ void scan_kernel()
{
    __shared__ int part[512];
    const int t = threadIdx.x;            // 512 threads, 512 cells each
    int s = 0;
    for (int k = 0; k < 512; k++) s += g_hist[t * 512 + k];
    part[t] = s;
    __syncthreads();
    if (t == 0) {
        int run = 0;
        for (int j = 0; j < 512; j++) { int tmp = part[j]; part[j] = run; run += tmp; }
    }
    __syncthreads();
    int base = part[t];
    for (int k = 0; k < 512; k++) {
        int c = t * 512 + k;
        int v = g_hist[c];
        g_off[c] = base;
        base += v;
    }
}

__global__ void scatter_kernel(const float* __restrict__ points, int n)
{
    int i = blockIdx.x * blockDim.x + threadIdx.x;
    if (i >= n) return;
    const int key = g_cell[i];
    const int dst = atomicAdd(&g_off[key], 1);
    g_perm[dst] = i;
    g_pts[3 * dst + 0] = points[3 * i + 0];
    g_pts[3 * dst + 1] = points[3 * i + 1];
    g_pts[3 * dst + 2] = points[3 * i + 2];
}

struct GridParams { int gs[NLEV]; };

// Fast softplus(100z)/100 (error audit in R8 — ~1e-6 abs on /100 output).
__device__ __forceinline__ float softplus100(float z)
{
    float x = 100.f * z;
    float t = __expf(-fabsf(x));
    return (fmaxf(x, 0.f) + __logf(1.f + t)) * 0.01f;
}

// Corner order: c = i*4 + j*2 + k (matches reference OFFSETS loop nest).
__device__ __forceinline__ void level_setup(int gs, float ux, float uy, float uz,
                                            unsigned idxs[8], float& wx, float& wy, float& wz)
{
    const float gm1 = (float)(gs - 1);
    const float fx = ux * gm1, fy = uy * gm1, fz = uz * gm1;
    int ix = (int)floorf(fx); ix = min(max(ix, 0), gs - 2);
    int iy = (int)floorf(fy); iy = min(max(iy, 0), gs - 2);
    int iz = (int)floorf(fz); iz = min(max(iz, 0), gs - 2);
    wx = fx - (float)ix;
    wy = fy - (float)iy;
    wz = fz - (float)iz;

    if ((long long)gs * gs * gs <= (long long)TSZ) {
        const int g1 = gs, g2 = gs * gs;
        const int base = ix + g1 * iy + g2 * iz;
        idxs[0] = base;
        idxs[1] = base + g2;
        idxs[2] = base + g1;
        idxs[3] = base + g1 + g2;
        idxs[4] = base + 1;
        idxs[5] = base + 1 + g2;
        idxs[6] = base + 1 + g1;
        idxs[7] = base + 1 + g1 + g2;
    } else {
        const unsigned hx0 = (unsigned)ix,               hx1 = hx0 + 1u;
        const unsigned hy0 = (unsigned)iy * 2654435761u, hy1 = hy0 + 2654435761u;
        const unsigned hz0 = (unsigned)iz * 805459861u,  hz1 = hz0 + 805459861u;
        const unsigned M = (unsigned)(TSZ - 1);
        idxs[0] = (hx0 ^ hy0 ^ hz0) & M;
        idxs[1] = (hx0 ^ hy0 ^ hz1) & M;
        idxs[2] = (hx0 ^ hy1 ^ hz0) & M;
        idxs[3] = (hx0 ^ hy1 ^ hz1) & M;
        idxs[4] = (hx1 ^ hy0 ^ hz0) & M;
        idxs[5] = (hx1 ^ hy0 ^ hz1) & M;
        idxs[6] = (hx1 ^ hy1 ^ hz0) & M;
        idxs[7] = (hx1 ^ hy1 ^ hz1) & M;
    }
}

__global__ __launch_bounds__(128, 5)
void sdf_kernel(const float* __restrict__ table,
                float* __restrict__ out,
                int n, GridParams gp)
{
    __shared__ ulonglong2 sW0[DIN][16];
    __shared__ ulonglong2 sW1[HIDDEN][16];
    __shared__ ulonglong2 sW2[HIDDEN][4];
    __shared__ ulonglong2 sb0[16];
    __shared__ ulonglong2 sb1[16];
    __shared__ ulonglong2 sb2[4];

    const int tid = threadIdx.x;
    for (int i = tid; i < DIN * 16;    i += 128) (&sW0[0][0])[i] = (&g_W0p[0][0])[i];
    for (int i = tid; i < HIDDEN * 16; i += 128) (&sW1[0][0])[i] = (&g_W1p[0][0])[i];
    for (int i = tid; i < HIDDEN * 4;  i += 128) (&sW2[0][0])[i] = (&g_W2p[0][0])[i];
    if (tid < 16) { sb0[tid] = g_b0p[tid]; sb1[tid] = g_b1p[tid]; }
    if (tid < 4)  { sb2[tid] = g_b2p[tid]; }
    __syncthreads();

    const int s = blockIdx.x * 128 + tid;
    if (s >= n) return;
    const int p = g_perm[s];

    const float px = g_pts[3 * s + 0];
    const float py = g_pts[3 * s + 1];
    const float pz = g_pts[3 * s + 2];
    const float ux = fminf(fmaxf((px + 1.f) * 0.5f, 0.f), 1.f);
    const float uy = fminf(fmaxf((py + 1.f) * 0.5f, 0.f), 1.f);
    const float uz = fminf(fmaxf((pz + 1.f) * 0.5f, 0.f), 1.f);

    const float2* __restrict__ tab = (const float2*)table;

    // ---- gather phase: per-level features into scalar regs --------------
    float enc[2 * NLEV];
    #pragma unroll
    for (int lv = 0; lv < NLEV; lv++) {
        unsigned idxs[8];
        float wx, wy, wz;
        level_setup(gp.gs[lv], ux, uy, uz, idxs, wx, wy, wz);
        const float2* __restrict__ tb = tab + (size_t)lv * TSZ;
        float2 f[8];
        #pragma unroll
        for (int c = 0; c < 8; c++) f[c] = __ldg(&tb[idxs[c]]);

        const float ox = 1.f - wx, oy = 1.f - wy, oz = 1.f - wz;
        const float w0 = ox * oy * oz,  w1 = ox * oy * wz;
        const float w2 = ox * wy * oz,  w3 = ox * wy * wz;
        const float w4 = wx * oy * oz,  w5 = wx * oy * wz;
        const float w6 = wx * wy * oz,  w7 = wx * wy * wz;
        enc[2 * lv]     = f[0].x * w0 + f[1].x * w1 + f[2].x * w2 + f[3].x * w3
                        + f[4].x * w4 + f[5].x * w5 + f[6].x * w6 + f[7].x * w7;
        enc[2 * lv + 1] = f[0].y * w0 + f[1].y * w1 + f[2].y * w2 + f[3].y * w3
                        + f[4].y * w4 + f[5].y * w5 + f[6].y * w6 + f[7].y * w7;
    }

    // ---- layer 0: two output halves (16 u64 acc live at a time) ---------
    float h[HIDDEN];
    #pragma unroll
    for (int half = 0; half < 2; half++) {
        u64 acc[16];
        #pragma unroll
        for (int q = 0; q < 8; q++) {
            const ulonglong2 b = sb0[8 * half + q];
            acc[2 * q] = b.x; acc[2 * q + 1] = b.y;
        }
        const u64 bx = bcast2(px), by = bcast2(py), bz = bcast2(pz);
        #pragma unroll
        for (int q = 0; q < 8; q++) {
            const ulonglong2 va = sW0[0][8 * half + q];
            const ulonglong2 vb = sW0[1][8 * half + q];
            const ulonglong2 vc = sW0[2][8 * half + q];
            acc[2 * q]     = fma2(bx, va.x, acc[2 * q]);
            acc[2 * q + 1] = fma2(bx, va.y, acc[2 * q + 1]);
            acc[2 * q]     = fma2(by, vb.x, acc[2 * q]);
            acc[2 * q + 1] = fma2(by, vb.y, acc[2 * q + 1]);
            acc[2 * q]     = fma2(bz, vc.x, acc[2 * q]);
            acc[2 * q + 1] = fma2(bz, vc.y, acc[2 * q + 1]);
        }
        #pragma unroll
        for (int lv = 0; lv < NLEV; lv++) {
            const int r = 3 + 2 * lv;
            const u64 bf0 = bcast2(enc[2 * lv]), bf1 = bcast2(enc[2 * lv + 1]);
            #pragma unroll
            for (int q = 0; q < 8; q++) {
                const ulonglong2 va = sW0[r][8 * half + q];
                const ulonglong2 vb = sW0[r + 1][8 * half + q];
                acc[2 * q]     = fma2(bf0, va.x, acc[2 * q]);
                acc[2 * q + 1] = fma2(bf0, va.y, acc[2 * q + 1]);
                acc[2 * q]     = fma2(bf1, vb.x, acc[2 * q]);
                acc[2 * q + 1] = fma2(bf1, vb.y, acc[2 * q + 1]);
            }
        }
        #pragma unroll
        for (int j = 0; j < 16; j++) {
            float lo, hi; unpack2(acc[j], lo, hi);
            h[32 * half + 2 * j]     = softplus100(lo);
            h[32 * half + 2 * j + 1] = softplus100(hi);
        }
    }

    // ---- layer 1: two output halves -------------------------------------
    float h1[HIDDEN];
    #pragma unroll
    for (int half = 0; half < 2; half++) {
        u64 acc1[16];
        #pragma unroll
        for (int q = 0; q < 8; q++) {
            const ulonglong2 b = sb1[8 * half + q];
            acc1[2 * q] = b.x; acc1[2 * q + 1] = b.y;
        }
        #pragma unroll 8
        for (int i = 0; i < HIDDEN; i++) {
            const u64 hb = bcast2(h[i]);
            #pragma unroll
            for (int q = 0; q < 8; q++) {
                const ulonglong2 v = sW1[i][8 * half + q];
                acc1[2 * q]     = fma2(hb, v.x, acc1[2 * q]);
                acc1[2 * q + 1] = fma2(hb, v.y, acc1[2 * q + 1]);
            }
        }
        #pragma unroll
        for (int j = 0; j < 16; j++) {
            float lo, hi; unpack2(acc1[j], lo, hi);
            h1[32 * half + 2 * j]     = softplus100(lo);
            h1[32 * half + 2 * j + 1] = softplus100(hi);
        }
    }

    // ---- layer 2 ---------------------------------------------------------
    u64 acc2[8];
    #pragma unroll
    for (int q = 0; q < 4; q++) {
        const ulonglong2 b = sb2[q];
        acc2[2 * q] = b.x; acc2[2 * q + 1] = b.y;
    }
    #pragma unroll 8
    for (int i = 0; i < HIDDEN; i++) {
        const u64 hb = bcast2(h1[i]);
        #pragma unroll
        for (int q = 0; q < 4; q++) {
            const ulonglong2 v = sW2[i][q];
            acc2[2 * q]     = fma2(hb, v.x, acc2[2 * q]);
            acc2[2 * q + 1] = fma2(hb, v.y, acc2[2 * q + 1]);
        }
    }

    float o2[16];
    #pragma unroll
    for (int j = 0; j < 8; j++) unpack2(acc2[j], o2[2 * j], o2[2 * j + 1]);

    out[p] = o2[0];
    float* __restrict__ hout = out + n + (size_t)p * FEAT;
    #pragma unroll
    for (int j = 0; j < FEAT; j++) hout[j] = o2[j];
}

extern "C" void kernel_launch(void* const* d_in, const int* in_sizes, int n_in,
                              void* d_out, int out_size)
{
    const float* points = (const float*)d_in[0];
    const float* table  = (const float*)d_in[1];
    const float* V0 = (const float*)d_in[2];
    const float* g0 = (const float*)d_in[3];
    const float* b0 = (const float*)d_in[4];
    const float* V1 = (const float*)d_in[5];
    const float* g1 = (const float*)d_in[6];
    const float* b1 = (const float*)d_in[7];
    const float* V2 = (const float*)d_in[8];
    const float* g2 = (const float*)d_in[9];
    const float* b2 = (const float*)d_in[10];
    float* out = (float*)d_out;

    const int n = in_sizes[0] / 3;

    GridParams gp;
    const double scale = exp((log(2048.0) - log(16.0)) / 15.0);
    for (int lv = 0; lv < NLEV; lv++)
        gp.gs[lv] = (int)floor(16.0 * pow(scale, (double)lv)) + 1;

    prep_kernel<<<1, 64>>>(V0, g0, b0, V1, g1, b1, V2, g2, b2);
    pack_kernel<<<1, 256>>>();

    zero_hist_kernel<<<(NBUCK + 255) / 256, 256>>>();
    assign_kernel<<<(n + 255) / 256, 256>>>(points, n);
    scan_kernel<<<1, 512>>>();
    scatter_kernel<<<(n + 255) / 256, 256>>>(points, n);

    const int blocks = (n + 127) / 128;
    sdf_kernel<<<blocks, 128>>>(table, out, n, gp);
}

// round 12
// speedup vs baseline: 1.3264x; 1.3264x over previous
#include <cuda_runtime.h>
#include <math.h>

#define NLEV   16
#define TSZ    524288
#define HIDDEN 64
#define FEAT   13
#define DIN    35

typedef unsigned long long u64;

__device__ __forceinline__ u64 pack2(float lo, float hi) {
    u64 r; asm("mov.b64 %0, {%1, %2};" : "=l"(r) : "f"(lo), "f"(hi)); return r;
}
__device__ __forceinline__ u64 bcast2(float v) { return pack2(v, v); }
__device__ __forceinline__ u64 fma2(u64 a, u64 b, u64 c) {
    u64 d; asm("fma.rn.f32x2 %0, %1, %2, %3;" : "=l"(d) : "l"(a), "l"(b), "l"(c)); return d;
}
__device__ __forceinline__ void unpack2(u64 v, float& lo, float& hi) {
    asm("mov.b64 {%0, %1}, %2;" : "=f"(lo), "=f"(hi) : "l"(v));
}

// ---------------------------------------------------------------------------
// Weight staging + value-packed ulonglong2 forms (native wide type, no punning)
// ---------------------------------------------------------------------------
__device__ float g_W0T[DIN][HIDDEN];
__device__ float g_W1T[HIDDEN][HIDDEN];
__device__ float g_W2T[HIDDEN][16];
__device__ float g_b0[HIDDEN];
__device__ float g_b1[HIDDEN];
__device__ float g_b2[16];

__device__ ulonglong2 g_W0p[DIN][16];
__device__ ulonglong2 g_W1p[HIDDEN][16];
__device__ ulonglong2 g_W2p[HIDDEN][4];
__device__ ulonglong2 g_b0p[16];
__device__ ulonglong2 g_b1p[16];
__device__ ulonglong2 g_b2p[4];

__global__ void prep_kernel(const float* __restrict__ V0, const float* __restrict__ g0, const float* __restrict__ b0,
                            const float* __restrict__ V1, const float* __restrict__ g1, const float* __restrict__ b1,
                            const float* __restrict__ V2, const float* __restrict__ g2, const float* __restrict__ b2)
{
    int o = threadIdx.x;
    if (o < HIDDEN) {
        float s = 0.f;
        for (int i = 0; i < DIN; i++) { float v = V0[o * DIN + i]; s += v * v; }
        float sc = g0[o] / sqrtf(s);
        for (int i = 0; i < DIN; i++) g_W0T[i][o] = V0[o * DIN + i] * sc;
        g_b0[o] = b0[o];

        s = 0.f;
        for (int i = 0; i < HIDDEN; i++) { float v = V1[o * HIDDEN + i]; s += v * v; }
        sc = g1[o] / sqrtf(s);
        for (int i = 0; i < HIDDEN; i++) g_W1T[i][o] = V1[o * HIDDEN + i] * sc;
        g_b1[o] = b1[o];
    }
    if (o < 16) {
        if (o < FEAT) {
            float s = 0.f;
            for (int i = 0; i < HIDDEN; i++) { float v = V2[o * HIDDEN + i]; s += v * v; }
            float sc = g2[o] / sqrtf(s);
            for (int i = 0; i < HIDDEN; i++) g_W2T[i][o] = V2[o * HIDDEN + i] * sc;
            g_b2[o] = b2[o];
        } else {
            for (int i = 0; i < HIDDEN; i++) g_W2T[i][o] = 0.f;
            g_b2[o] = 0.f;
        }
    }
}

__device__ __forceinline__ ulonglong2 pack4(const float* s) {
    ulonglong2 v;
    v.x = ((u64)__float_as_uint(s[1]) << 32) | (u64)__float_as_uint(s[0]);
    v.y = ((u64)__float_as_uint(s[3]) << 32) | (u64)__float_as_uint(s[2]);
    return v;
}

__global__ void pack_kernel()
{
    const int NW0 = DIN * 16, NW1 = HIDDEN * 16, NW2 = HIDDEN * 4;
    const int total = NW0 + NW1 + NW2 + 16 + 16 + 4;
    for (int e = threadIdx.x; e < total; e += blockDim.x) {
        int r = e;
        if (r < NW0) { (&g_W0p[0][0])[r] = pack4(&(&g_W0T[0][0])[4 * r]); continue; }
        r -= NW0;
        if (r < NW1) { (&g_W1p[0][0])[r] = pack4(&(&g_W1T[0][0])[4 * r]); continue; }
        r -= NW1;
        if (r < NW2) { (&g_W2p[0][0])[r] = pack4(&(&g_W2T[0][0])[4 * r]); continue; }
        r -= NW2;
        if (r < 16) { g_b0p[r] = pack4(&g_b0[4 * r]); continue; }
        r -= 16;
        if (r < 16) { g_b1p[r] = pack4(&g_b1[4 * r]); continue; }
        r -= 16;
        g_b2p[r] = pack4(&g_b2[4 * r]);
    }
}

struct GridParams { int gs[NLEV]; };

// Fast softplus(100z)/100 (error audit in R8 — ~1e-6 abs on /100 output).
__device__ __forceinline__ float softplus100(float z)
{
    float x = 100.f * z;
    float t = __expf(-fabsf(x));
    return (fmaxf(x, 0.f) + __logf(1.f + t)) * 0.01f;
}

// Corner order: c = i*4 + j*2 + k (matches reference OFFSETS loop nest).
__device__ __forceinline__ void level_setup(int gs, float ux, float uy, float uz,
                                            unsigned idxs[8], float& wx, float& wy, float& wz)
{
    const float gm1 = (float)(gs - 1);
    const float fx = ux * gm1, fy = uy * gm1, fz = uz * gm1;
    int ix = (int)floorf(fx); ix = min(max(ix, 0), gs - 2);
    int iy = (int)floorf(fy); iy = min(max(iy, 0), gs - 2);
    int iz = (int)floorf(fz); iz = min(max(iz, 0), gs - 2);
    wx = fx - (float)ix;
    wy = fy - (float)iy;
    wz = fz - (float)iz;

    if ((long long)gs * gs * gs <= (long long)TSZ) {
        const int g1 = gs, g2 = gs * gs;
        const int base = ix + g1 * iy + g2 * iz;
        idxs[0] = base;
        idxs[1] = base + g2;
        idxs[2] = base + g1;
        idxs[3] = base + g1 + g2;
        idxs[4] = base + 1;
        idxs[5] = base + 1 + g2;
        idxs[6] = base + 1 + g1;
        idxs[7] = base + 1 + g1 + g2;
    } else {
        const unsigned hx0 = (unsigned)ix,               hx1 = hx0 + 1u;
        const unsigned hy0 = (unsigned)iy * 2654435761u, hy1 = hy0 + 2654435761u;
        const unsigned hz0 = (unsigned)iz * 805459861u,  hz1 = hz0 + 805459861u;
        const unsigned M = (unsigned)(TSZ - 1);
        idxs[0] = (hx0 ^ hy0 ^ hz0) & M;
        idxs[1] = (hx0 ^ hy0 ^ hz1) & M;
        idxs[2] = (hx0 ^ hy1 ^ hz0) & M;
        idxs[3] = (hx0 ^ hy1 ^ hz1) & M;
        idxs[4] = (hx1 ^ hy0 ^ hz0) & M;
        idxs[5] = (hx1 ^ hy0 ^ hz1) & M;
        idxs[6] = (hx1 ^ hy1 ^ hz0) & M;
        idxs[7] = (hx1 ^ hy1 ^ hz1) & M;
    }
}

__global__ __launch_bounds__(128, 5)
void sdf_kernel(const float* __restrict__ points,
                const float* __restrict__ table,
                float* __restrict__ out,
                int n, GridParams gp)
{
    __shared__ ulonglong2 sW0[DIN][16];
    __shared__ ulonglong2 sW1[HIDDEN][16];
    __shared__ ulonglong2 sW2[HIDDEN][4];
    __shared__ ulonglong2 sb0[16];
    __shared__ ulonglong2 sb1[16];
    __shared__ ulonglong2 sb2[4];
    __shared__ float sOut[128 * FEAT];   // staged h outputs for coalesced store

    const int tid = threadIdx.x;
    for (int i = tid; i < DIN * 16;    i += 128) (&sW0[0][0])[i] = (&g_W0p[0][0])[i];
    for (int i = tid; i < HIDDEN * 16; i += 128) (&sW1[0][0])[i] = (&g_W1p[0][0])[i];
    for (int i = tid; i < HIDDEN * 4;  i += 128) (&sW2[0][0])[i] = (&g_W2p[0][0])[i];
    if (tid < 16) { sb0[tid] = g_b0p[tid]; sb1[tid] = g_b1p[tid]; }
    if (tid < 4)  { sb2[tid] = g_b2p[tid]; }
    __syncthreads();

    const int p = blockIdx.x * 128 + tid;

    if (p < n) {
        const float px = points[3 * p + 0];
        const float py = points[3 * p + 1];
        const float pz = points[3 * p + 2];
        const float ux = fminf(fmaxf((px + 1.f) * 0.5f, 0.f), 1.f);
        const float uy = fminf(fmaxf((py + 1.f) * 0.5f, 0.f), 1.f);
        const float uz = fminf(fmaxf((pz + 1.f) * 0.5f, 0.f), 1.f);

        const float2* __restrict__ tab = (const float2*)table;

        // ---- gather phase: per-level features into scalar regs ----------
        float enc[2 * NLEV];
        #pragma unroll
        for (int lv = 0; lv < NLEV; lv++) {
            unsigned idxs[8];
            float wx, wy, wz;
            level_setup(gp.gs[lv], ux, uy, uz, idxs, wx, wy, wz);
            const float2* __restrict__ tb = tab + (size_t)lv * TSZ;
            float2 f[8];
            #pragma unroll
            for (int c = 0; c < 8; c++) f[c] = __ldg(&tb[idxs[c]]);

            const float ox = 1.f - wx, oy = 1.f - wy, oz = 1.f - wz;
            const float w0 = ox * oy * oz,  w1 = ox * oy * wz;
            const float w2 = ox * wy * oz,  w3 = ox * wy * wz;
            const float w4 = wx * oy * oz,  w5 = wx * oy * wz;
            const float w6 = wx * wy * oz,  w7 = wx * wy * wz;
            enc[2 * lv]     = f[0].x * w0 + f[1].x * w1 + f[2].x * w2 + f[3].x * w3
                            + f[4].x * w4 + f[5].x * w5 + f[6].x * w6 + f[7].x * w7;
            enc[2 * lv + 1] = f[0].y * w0 + f[1].y * w1 + f[2].y * w2 + f[3].y * w3
                            + f[4].y * w4 + f[5].y * w5 + f[6].y * w6 + f[7].y * w7;
        }

        // ---- layer 0: two output halves (16 u64 acc live at a time) -----
        float h[HIDDEN];
        #pragma unroll
        for (int half = 0; half < 2; half++) {
            u64 acc[16];
            #pragma unroll
            for (int q = 0; q < 8; q++) {
                const ulonglong2 b = sb0[8 * half + q];
                acc[2 * q] = b.x; acc[2 * q + 1] = b.y;
            }
            const u64 bx = bcast2(px), by = bcast2(py), bz = bcast2(pz);
            #pragma unroll
            for (int q = 0; q < 8; q++) {
                const ulonglong2 va = sW0[0][8 * half + q];
                const ulonglong2 vb = sW0[1][8 * half + q];
                const ulonglong2 vc = sW0[2][8 * half + q];
                acc[2 * q]     = fma2(bx, va.x, acc[2 * q]);
                acc[2 * q + 1] = fma2(bx, va.y, acc[2 * q + 1]);
                acc[2 * q]     = fma2(by, vb.x, acc[2 * q]);
                acc[2 * q + 1] = fma2(by, vb.y, acc[2 * q + 1]);
                acc[2 * q]     = fma2(bz, vc.x, acc[2 * q]);
                acc[2 * q + 1] = fma2(bz, vc.y, acc[2 * q + 1]);
            }
            #pragma unroll
            for (int lv = 0; lv < NLEV; lv++) {
                const int r = 3 + 2 * lv;
                const u64 bf0 = bcast2(enc[2 * lv]), bf1 = bcast2(enc[2 * lv + 1]);
                #pragma unroll
                for (int q = 0; q < 8; q++) {
                    const ulonglong2 va = sW0[r][8 * half + q];
                    const ulonglong2 vb = sW0[r + 1][8 * half + q];
                    acc[2 * q]     = fma2(bf0, va.x, acc[2 * q]);
                    acc[2 * q + 1] = fma2(bf0, va.y, acc[2 * q + 1]);
                    acc[2 * q]     = fma2(bf1, vb.x, acc[2 * q]);
                    acc[2 * q + 1] = fma2(bf1, vb.y, acc[2 * q + 1]);
                }
            }
            #pragma unroll
            for (int j = 0; j < 16; j++) {
                float lo, hi; unpack2(acc[j], lo, hi);
                h[32 * half + 2 * j]     = softplus100(lo);
                h[32 * half + 2 * j + 1] = softplus100(hi);
            }
        }

        // ---- layer 1: two output halves ---------------------------------
        float h1[HIDDEN];
        #pragma unroll
        for (int half = 0; half < 2; half++) {
            u64 acc1[16];
            #pragma unroll
            for (int q = 0; q < 8; q++) {
                const ulonglong2 b = sb1[8 * half + q];
                acc1[2 * q] = b.x; acc1[2 * q + 1] = b.y;
            }
            #pragma unroll 8
            for (int i = 0; i < HIDDEN; i++) {
                const u64 hb = bcast2(h[i]);
                #pragma unroll
                for (int q = 0; q < 8; q++) {
                    const ulonglong2 v = sW1[i][8 * half + q];
                    acc1[2 * q]     = fma2(hb, v.x, acc1[2 * q]);
                    acc1[2 * q + 1] = fma2(hb, v.y, acc1[2 * q + 1]);
                }
            }
            #pragma unroll
            for (int j = 0; j < 16; j++) {
                float lo, hi; unpack2(acc1[j], lo, hi);
                h1[32 * half + 2 * j]     = softplus100(lo);
                h1[32 * half + 2 * j + 1] = softplus100(hi);
            }
        }

        // ---- layer 2 -----------------------------------------------------
        u64 acc2[8];
        #pragma unroll
        for (int q = 0; q < 4; q++) {
            const ulonglong2 b = sb2[q];
            acc2[2 * q] = b.x; acc2[2 * q + 1] = b.y;
        }
        #pragma unroll 8
        for (int i = 0; i < HIDDEN; i++) {
            const u64 hb = bcast2(h1[i]);
            #pragma unroll
            for (int q = 0; q < 4; q++) {
                const ulonglong2 v = sW2[i][q];
                acc2[2 * q]     = fma2(hb, v.x, acc2[2 * q]);
                acc2[2 * q + 1] = fma2(hb, v.y, acc2[2 * q + 1]);
            }
        }

        float o2[16];
        #pragma unroll
        for (int j = 0; j < 8; j++) unpack2(acc2[j], o2[2 * j], o2[2 * j + 1]);

        // sdf output is already coalesced (p linear within block)
        out[p] = o2[0];
        // stage the 13 h outputs (stride 13 is coprime with 32 -> no conflicts)
        #pragma unroll
        for (int j = 0; j < FEAT; j++) sOut[tid * FEAT + j] = o2[j];
    }

    __syncthreads();

    // cooperative coalesced store of the block's h outputs
    const int base = blockIdx.x * 128;
    const int cnt = min(128, n - base);
    if (cnt > 0) {
        float* __restrict__ dst = out + n + (size_t)base * FEAT;
        const int total = cnt * FEAT;
        for (int i = tid; i < total; i += 128) dst[i] = sOut[i];
    }
}

extern "C" void kernel_launch(void* const* d_in, const int* in_sizes, int n_in,
                              void* d_out, int out_size)
{
    const float* points = (const float*)d_in[0];
    const float* table  = (const float*)d_in[1];
    const float* V0 = (const float*)d_in[2];
    const float* g0 = (const float*)d_in[3];
    const float* b0 = (const float*)d_in[4];
    const float* V1 = (const float*)d_in[5];
    const float* g1 = (const float*)d_in[6];
    const float* b1 = (const float*)d_in[7];
    const float* V2 = (const float*)d_in[8];
    const float* g2 = (const float*)d_in[9];
    const float* b2 = (const float*)d_in[10];
    float* out = (float*)d_out;

    const int n = in_sizes[0] / 3;

    GridParams gp;
    const double scale = exp((log(2048.0) - log(16.0)) / 15.0);
    for (int lv = 0; lv < NLEV; lv++)
        gp.gs[lv] = (int)floor(16.0 * pow(scale, (double)lv)) + 1;

    prep_kernel<<<1, 64>>>(V0, g0, b0, V1, g1, b1, V2, g2, b2);
    pack_kernel<<<1, 256>>>();

    const int blocks = (n + 127) / 128;
    sdf_kernel<<<blocks, 128>>>(points, table, out, n, gp);
}

// round 13
// speedup vs baseline: 1.5770x; 1.1890x over previous
#include <cuda_runtime.h>
#include <math.h>

#define NLEV   16
#define TSZ    524288
#define HIDDEN 64
#define FEAT   13
#define DIN    35
#define MAXDENSE 340000   // sum gs^3 for dense levels (17,23,31,43,59) = 331,757

typedef unsigned long long u64;

__device__ __forceinline__ u64 pack2(float lo, float hi) {
    u64 r; asm("mov.b64 %0, {%1, %2};" : "=l"(r) : "f"(lo), "f"(hi)); return r;
}
__device__ __forceinline__ u64 bcast2(float v) { return pack2(v, v); }
__device__ __forceinline__ u64 fma2(u64 a, u64 b, u64 c) {
    u64 d; asm("fma.rn.f32x2 %0, %1, %2, %3;" : "=l"(d) : "l"(a), "l"(b), "l"(c)); return d;
}
__device__ __forceinline__ void unpack2(u64 v, float& lo, float& hi) {
    asm("mov.b64 {%0, %1}, %2;" : "=f"(lo), "=f"(hi) : "l"(v));
}

// ---------------------------------------------------------------------------
// Weight staging + value-packed ulonglong2 forms (native wide type, no punning)
// ---------------------------------------------------------------------------
__device__ float g_W0T[DIN][HIDDEN];
__device__ float g_W1T[HIDDEN][HIDDEN];
__device__ float g_W2T[HIDDEN][16];
__device__ float g_b0[HIDDEN];
__device__ float g_b1[HIDDEN];
__device__ float g_b2[16];

__device__ ulonglong2 g_W0p[DIN][16];
__device__ ulonglong2 g_W1p[HIDDEN][16];
__device__ ulonglong2 g_W2p[HIDDEN][4];
__device__ ulonglong2 g_b0p[16];
__device__ ulonglong2 g_b1p[16];
__device__ ulonglong2 g_b2p[4];

// Paired-corner tables for dense levels: g_dense4[off+idx] = (tab[idx], tab[idx+1])
__device__ float4 g_dense4[MAXDENSE];

struct GridParams {
    int gs[NLEV];
    int doff[NLEV];      // float4 offset into g_dense4, or -1 if hashed
    int dtotal;          // total dense cells
};

__global__ void prep_kernel(const float* __restrict__ V0, const float* __restrict__ g0, const float* __restrict__ b0,
                            const float* __restrict__ V1, const float* __restrict__ g1, const float* __restrict__ b1,
                            const float* __restrict__ V2, const float* __restrict__ g2, const float* __restrict__ b2)
{
    int o = threadIdx.x;
    if (o < HIDDEN) {
        float s = 0.f;
        for (int i = 0; i < DIN; i++) { float v = V0[o * DIN + i]; s += v * v; }
        float sc = g0[o] / sqrtf(s);
        for (int i = 0; i < DIN; i++) g_W0T[i][o] = V0[o * DIN + i] * sc;
        g_b0[o] = b0[o];

        s = 0.f;
        for (int i = 0; i < HIDDEN; i++) { float v = V1[o * HIDDEN + i]; s += v * v; }
        sc = g1[o] / sqrtf(s);
        for (int i = 0; i < HIDDEN; i++) g_W1T[i][o] = V1[o * HIDDEN + i] * sc;
        g_b1[o] = b1[o];
    }
    if (o < 16) {
        if (o < FEAT) {
            float s = 0.f;
            for (int i = 0; i < HIDDEN; i++) { float v = V2[o * HIDDEN + i]; s += v * v; }
            float sc = g2[o] / sqrtf(s);
            for (int i = 0; i < HIDDEN; i++) g_W2T[i][o] = V2[o * HIDDEN + i] * sc;
            g_b2[o] = b2[o];
        } else {
            for (int i = 0; i < HIDDEN; i++) g_W2T[i][o] = 0.f;
            g_b2[o] = 0.f;
        }
    }
}

__device__ __forceinline__ ulonglong2 pack4(const float* s) {
    ulonglong2 v;
    v.x = ((u64)__float_as_uint(s[1]) << 32) | (u64)__float_as_uint(s[0]);
    v.y = ((u64)__float_as_uint(s[3]) << 32) | (u64)__float_as_uint(s[2]);
    return v;
}

__global__ void pack_kernel()
{
    const int NW0 = DIN * 16, NW1 = HIDDEN * 16, NW2 = HIDDEN * 4;
    const int total = NW0 + NW1 + NW2 + 16 + 16 + 4;
    for (int e = threadIdx.x; e < total; e += blockDim.x) {
        int r = e;
        if (r < NW0) { (&g_W0p[0][0])[r] = pack4(&(&g_W0T[0][0])[4 * r]); continue; }
        r -= NW0;
        if (r < NW1) { (&g_W1p[0][0])[r] = pack4(&(&g_W1T[0][0])[4 * r]); continue; }
        r -= NW1;
        if (r < NW2) { (&g_W2p[0][0])[r] = pack4(&(&g_W2T[0][0])[4 * r]); continue; }
        r -= NW2;
        if (r < 16) { g_b0p[r] = pack4(&g_b0[4 * r]); continue; }
        r -= 16;
        if (r < 16) { g_b1p[r] = pack4(&g_b1[4 * r]); continue; }
        r -= 16;
        g_b2p[r] = pack4(&g_b2[4 * r]);
    }
}

// Build paired-corner dense tables.
// For cell idx of dense level lv: pair = (tab[lv*TSZ+idx], tab[lv*TSZ+idx+1]).
// idx+1 <= gs^3 <= TSZ stays inside the level's slab (last pair's 2nd half
// is never consumed: interpolation uses idx+1 only when idx+1 < gs^3).
__global__ void repack_kernel(const float* __restrict__ table, GridParams gp)
{
    const float2* __restrict__ tab = (const float2*)table;
    for (int i = blockIdx.x * blockDim.x + threadIdx.x; i < gp.dtotal;
         i += gridDim.x * blockDim.x) {
        // find the dense level containing global cell i
        #pragma unroll
        for (int lv = 0; lv < NLEV; lv++) {
            if (gp.doff[lv] < 0) continue;
            const int gs = gp.gs[lv];
            const int ncell = gs * gs * gs;
            const int rel = i - gp.doff[lv];
            if (rel >= 0 && rel < ncell) {
                const float2 a = tab[(size_t)lv * TSZ + rel];
                const float2 b = tab[(size_t)lv * TSZ + rel + 1];
                g_dense4[i] = make_float4(a.x, a.y, b.x, b.y);
            }
        }
    }
}

// Fast softplus(100z)/100 (error audit in R8 — ~1e-6 abs on /100 output).
__device__ __forceinline__ float softplus100(float z)
{
    float x = 100.f * z;
    float t = __expf(-fabsf(x));
    return (fmaxf(x, 0.f) + __logf(1.f + t)) * 0.01f;
}

__global__ __launch_bounds__(128, 5)
void sdf_kernel(const float* __restrict__ points,
                const float* __restrict__ table,
                float* __restrict__ out,
                int n, GridParams gp)
{
    __shared__ ulonglong2 sW0[DIN][16];
    __shared__ ulonglong2 sW1[HIDDEN][16];
    __shared__ ulonglong2 sW2[HIDDEN][4];
    __shared__ ulonglong2 sb0[16];
    __shared__ ulonglong2 sb1[16];
    __shared__ ulonglong2 sb2[4];

    const int tid = threadIdx.x;
    for (int i = tid; i < DIN * 16;    i += 128) (&sW0[0][0])[i] = (&g_W0p[0][0])[i];
    for (int i = tid; i < HIDDEN * 16; i += 128) (&sW1[0][0])[i] = (&g_W1p[0][0])[i];
    for (int i = tid; i < HIDDEN * 4;  i += 128) (&sW2[0][0])[i] = (&g_W2p[0][0])[i];
    if (tid < 16) { sb0[tid] = g_b0p[tid]; sb1[tid] = g_b1p[tid]; }
    if (tid < 4)  { sb2[tid] = g_b2p[tid]; }
    __syncthreads();

    const int p = blockIdx.x * 128 + tid;
    if (p >= n) return;

    const float px = points[3 * p + 0];
    const float py = points[3 * p + 1];
    const float pz = points[3 * p + 2];
    const float ux = fminf(fmaxf((px + 1.f) * 0.5f, 0.f), 1.f);
    const float uy = fminf(fmaxf((py + 1.f) * 0.5f, 0.f), 1.f);
    const float uz = fminf(fmaxf((pz + 1.f) * 0.5f, 0.f), 1.f);

    const float2* __restrict__ tab = (const float2*)table;
    const float4* __restrict__ dtab = (const float4*)g_dense4;

    // ---- gather phase: per-level features into scalar regs --------------
    float enc[2 * NLEV];
    #pragma unroll
    for (int lv = 0; lv < NLEV; lv++) {
        const int gs = gp.gs[lv];
        const float gm1 = (float)(gs - 1);
        const float fx = ux * gm1, fy = uy * gm1, fz = uz * gm1;
        int ix = (int)floorf(fx); ix = min(max(ix, 0), gs - 2);
        int iy = (int)floorf(fy); iy = min(max(iy, 0), gs - 2);
        int iz = (int)floorf(fz); iz = min(max(iz, 0), gs - 2);
        const float wx = fx - (float)ix;
        const float wy = fy - (float)iy;
        const float wz = fz - (float)iz;

        float2 f[8];   // c = i*4 + j*2 + k
        if (gp.doff[lv] >= 0) {
            // dense: one float4 per (j,k) pair covers corners i=0 and i=1
            const int g1 = gs, g2 = gs * gs;
            const int base = ix + g1 * iy + g2 * iz;
            const float4* __restrict__ dl = dtab + gp.doff[lv];
            const float4 q0 = __ldg(&dl[base]);
            const float4 q1 = __ldg(&dl[base + g2]);
            const float4 q2 = __ldg(&dl[base + g1]);
            const float4 q3 = __ldg(&dl[base + g1 + g2]);
            f[0] = make_float2(q0.x, q0.y); f[4] = make_float2(q0.z, q0.w);
            f[1] = make_float2(q1.x, q1.y); f[5] = make_float2(q1.z, q1.w);
            f[2] = make_float2(q2.x, q2.y); f[6] = make_float2(q2.z, q2.w);
            f[3] = make_float2(q3.x, q3.y); f[7] = make_float2(q3.z, q3.w);
        } else {
            const unsigned hx0 = (unsigned)ix,               hx1 = hx0 + 1u;
            const unsigned hy0 = (unsigned)iy * 2654435761u, hy1 = hy0 + 2654435761u;
            const unsigned hz0 = (unsigned)iz * 805459861u,  hz1 = hz0 + 805459861u;
            const unsigned M = (unsigned)(TSZ - 1);
            unsigned idxs[8];
            idxs[0] = (hx0 ^ hy0 ^ hz0) & M;
            idxs[1] = (hx0 ^ hy0 ^ hz1) & M;
            idxs[2] = (hx0 ^ hy1 ^ hz0) & M;
            idxs[3] = (hx0 ^ hy1 ^ hz1) & M;
            idxs[4] = (hx1 ^ hy0 ^ hz0) & M;
            idxs[5] = (hx1 ^ hy0 ^ hz1) & M;
            idxs[6] = (hx1 ^ hy1 ^ hz0) & M;
            idxs[7] = (hx1 ^ hy1 ^ hz1) & M;
            const float2* __restrict__ tb = tab + (size_t)lv * TSZ;
            #pragma unroll
            for (int c = 0; c < 8; c++) f[c] = __ldg(&tb[idxs[c]]);
        }

        const float ox = 1.f - wx, oy = 1.f - wy, oz = 1.f - wz;
        const float w0 = ox * oy * oz,  w1 = ox * oy * wz;
        const float w2 = ox * wy * oz,  w3 = ox * wy * wz;
        const float w4 = wx * oy * oz,  w5 = wx * oy * wz;
        const float w6 = wx * wy * oz,  w7 = wx * wy * wz;
        enc[2 * lv]     = f[0].x * w0 + f[1].x * w1 + f[2].x * w2 + f[3].x * w3
                        + f[4].x * w4 + f[5].x * w5 + f[6].x * w6 + f[7].x * w7;
        enc[2 * lv + 1] = f[0].y * w0 + f[1].y * w1 + f[2].y * w2 + f[3].y * w3
                        + f[4].y * w4 + f[5].y * w5 + f[6].y * w6 + f[7].y * w7;
    }

    // ---- layer 0: two output halves (16 u64 acc live at a time) ---------
    float h[HIDDEN];
    #pragma unroll
    for (int half = 0; half < 2; half++) {
        u64 acc[16];
        #pragma unroll
        for (int q = 0; q < 8; q++) {
            const ulonglong2 b = sb0[8 * half + q];
            acc[2 * q] = b.x; acc[2 * q + 1] = b.y;
        }
        const u64 bx = bcast2(px), by = bcast2(py), bz = bcast2(pz);
        #pragma unroll
        for (int q = 0; q < 8; q++) {
            const ulonglong2 va = sW0[0][8 * half + q];
            const ulonglong2 vb = sW0[1][8 * half + q];
            const ulonglong2 vc = sW0[2][8 * half + q];
            acc[2 * q]     = fma2(bx, va.x, acc[2 * q]);
            acc[2 * q + 1] = fma2(bx, va.y, acc[2 * q + 1]);
            acc[2 * q]     = fma2(by, vb.x, acc[2 * q]);
            acc[2 * q + 1] = fma2(by, vb.y, acc[2 * q + 1]);
            acc[2 * q]     = fma2(bz, vc.x, acc[2 * q]);
            acc[2 * q + 1] = fma2(bz, vc.y, acc[2 * q + 1]);
        }
        #pragma unroll
        for (int lv = 0; lv < NLEV; lv++) {
            const int r = 3 + 2 * lv;
            const u64 bf0 = bcast2(enc[2 * lv]), bf1 = bcast2(enc[2 * lv + 1]);
            #pragma unroll
            for (int q = 0; q < 8; q++) {
                const ulonglong2 va = sW0[r][8 * half + q];
                const ulonglong2 vb = sW0[r + 1][8 * half + q];
                acc[2 * q]     = fma2(bf0, va.x, acc[2 * q]);
                acc[2 * q + 1] = fma2(bf0, va.y, acc[2 * q + 1]);
                acc[2 * q]     = fma2(bf1, vb.x, acc[2 * q]);
                acc[2 * q + 1] = fma2(bf1, vb.y, acc[2 * q + 1]);
            }
        }
        #pragma unroll
        for (int j = 0; j < 16; j++) {
            float lo, hi; unpack2(acc[j], lo, hi);
            h[32 * half + 2 * j]     = softplus100(lo);
            h[32 * half + 2 * j + 1] = softplus100(hi);
        }
    }

    // ---- layer 1: two output halves -------------------------------------
    float h1[HIDDEN];
    #pragma unroll
    for (int half = 0; half < 2; half++) {
        u64 acc1[16];
        #pragma unroll
        for (int q = 0; q < 8; q++) {
            const ulonglong2 b = sb1[8 * half + q];
            acc1[2 * q] = b.x; acc1[2 * q + 1] = b.y;
        }
        #pragma unroll 8
        for (int i = 0; i < HIDDEN; i++) {
            const u64 hb = bcast2(h[i]);
            #pragma unroll
            for (int q = 0; q < 8; q++) {
                const ulonglong2 v = sW1[i][8 * half + q];
                acc1[2 * q]     = fma2(hb, v.x, acc1[2 * q]);
                acc1[2 * q + 1] = fma2(hb, v.y, acc1[2 * q + 1]);
            }
        }
        #pragma unroll
        for (int j = 0; j < 16; j++) {
            float lo, hi; unpack2(acc1[j], lo, hi);
            h1[32 * half + 2 * j]     = softplus100(lo);
            h1[32 * half + 2 * j + 1] = softplus100(hi);
        }
    }

    // ---- layer 2 ---------------------------------------------------------
    u64 acc2[8];
    #pragma unroll
    for (int q = 0; q < 4; q++) {
        const ulonglong2 b = sb2[q];
        acc2[2 * q] = b.x; acc2[2 * q + 1] = b.y;
    }
    #pragma unroll 8
    for (int i = 0; i < HIDDEN; i++) {
        const u64 hb = bcast2(h1[i]);
        #pragma unroll
        for (int q = 0; q < 4; q++) {
            const ulonglong2 v = sW2[i][q];
            acc2[2 * q]     = fma2(hb, v.x, acc2[2 * q]);
            acc2[2 * q + 1] = fma2(hb, v.y, acc2[2 * q + 1]);
        }
    }

    float o2[16];
    #pragma unroll
    for (int j = 0; j < 8; j++) unpack2(acc2[j], o2[2 * j], o2[2 * j + 1]);

    out[p] = o2[0];
    float* __restrict__ hout = out + n + (size_t)p * FEAT;
    #pragma unroll
    for (int j = 0; j < FEAT; j++) hout[j] = o2[j];
}

extern "C" void kernel_launch(void* const* d_in, const int* in_sizes, int n_in,
                              void* d_out, int out_size)
{
    const float* points = (const float*)d_in[0];
    const float* table  = (const float*)d_in[1];
    const float* V0 = (const float*)d_in[2];
    const float* g0 = (const float*)d_in[3];
    const float* b0 = (const float*)d_in[4];
    const float* V1 = (const float*)d_in[5];
    const float* g1 = (const float*)d_in[6];
    const float* b1 = (const float*)d_in[7];
    const float* V2 = (const float*)d_in[8];
    const float* g2 = (const float*)d_in[9];
    const float* b2 = (const float*)d_in[10];
    float* out = (float*)d_out;

    const int n = in_sizes[0] / 3;

    GridParams gp;
    const double scale = exp((log(2048.0) - log(16.0)) / 15.0);
    int run = 0;
    for (int lv = 0; lv < NLEV; lv++) {
        const int gs = (int)floor(16.0 * pow(scale, (double)lv)) + 1;
        gp.gs[lv] = gs;
        const long long ncell = (long long)gs * gs * gs;
        if (ncell <= (long long)TSZ && run + ncell <= MAXDENSE) {
            gp.doff[lv] = run;
            run += (int)ncell;
        } else {
            gp.doff[lv] = -1;
        }
    }
    gp.dtotal = run;

    prep_kernel<<<1, 64>>>(V0, g0, b0, V1, g1, b1, V2, g2, b2);
    pack_kernel<<<1, 256>>>();
    repack_kernel<<<512, 256>>>(table, gp);

    const int blocks = (n + 127) / 128;
    sdf_kernel<<<blocks, 128>>>(points, table, out, n, gp);
}